// round 12
// baseline (speedup 1.0000x reference)
#include <cuda_runtime.h>
#include <cuda_bf16.h>
#include <cuda_fp16.h>
#include <math.h>
#include <stdint.h>

// Problem constants
#define B_SZ 512
#define T_SZ 64
#define I_SZ 64
#define H_SZ 128
#define G_SZ 384   // 3*H

// ---------------- device scratch (no allocations allowed) ----------------
__device__ uint32_t g_P [I_SZ * 24576];             // per-feature W_hh, fp16 paired-fragment layout
__device__ float g_hs[B_SZ * I_SZ * H_SZ];          // GRU final hidden
__device__ float g_A [B_SZ * I_SZ * H_SZ];          // xT
__device__ float g_Wt[7 * H_SZ * H_SZ];             // transposed tail weights

__device__ __forceinline__ void mma_f16(float* d, const uint32_t* a, uint32_t b0, uint32_t b1) {
    asm volatile(
        "mma.sync.aligned.m16n8k16.row.col.f32.f16.f16.f32 "
        "{%0,%1,%2,%3}, {%4,%5,%6,%7}, {%8,%9}, {%0,%1,%2,%3};"
        : "+f"(d[0]), "+f"(d[1]), "+f"(d[2]), "+f"(d[3])
        : "r"(a[0]), "r"(a[1]), "r"(a[2]), "r"(a[3]), "r"(b0), "r"(b1));
}

__device__ __forceinline__ __half2 tanh2(__half2 v) {
    uint32_t o, in = *reinterpret_cast<uint32_t*>(&v);
    asm("tanh.approx.f16x2 %0, %1;" : "=r"(o) : "r"(in));
    return *reinterpret_cast<__half2*>(&o);
}

// ---------------- pack W_hh: fp16, nA-paired B-fragment layout, r/z rows pre-scaled 0.5 ----------------
// P[i][ (((w*3+g3)*8+kt)*32 + lane)*4 + s ], s: nA = s>>1, reg = s&1
// k0 = 16kt + 8reg + 2(lane&3) ; j = 16w + 8nA + (lane>>2) ; row = g3*128 + j
__global__ void pack_whh_kernel(const float* __restrict__ W_hh, uint32_t* __restrict__ P)
{
    int idx = blockIdx.x * blockDim.x + threadIdx.x;
    if (idx >= I_SZ * 24576) return;
    int i = idx / 24576;
    int r = idx % 24576;
    int w  = r / 3072; r %= 3072;
    int g3 = r / 1024; r %= 1024;
    int kt = r / 128;  r %= 128;
    int lane = r >> 2;
    int s = r & 3;
    int nA = s >> 1, reg = s & 1;
    int k0 = 16 * kt + 8 * reg + 2 * (lane & 3);
    int j  = 16 * w + 8 * nA + (lane >> 2);
    float scale = (g3 < 2) ? 0.5f : 1.0f;   // fold sigmoid's /2 into r,z weights
    const float* src = W_hh + ((size_t)i * G_SZ + g3 * 128 + j) * H_SZ + k0;
    __half2 h2 = __floats2half2_rn(scale * src[0], scale * src[1]);
    P[idx] = *reinterpret_cast<uint32_t*>(&h2);
}

// ---------------- transpose x: xT[t][i][b] = x[b][t][i] ----------------
__global__ void xt_kernel(const float* __restrict__ x, float* __restrict__ xT)
{
    int idx = blockIdx.x * blockDim.x + threadIdx.x;
    if (idx >= B_SZ * T_SZ * I_SZ) return;
    int b = idx & 511;
    int r = idx >> 9;
    int i = r & 63;
    int t = r >> 6;
    xT[idx] = x[((size_t)b * T_SZ + t) * I_SZ + i];
}

// ---------------- transpose the 7 [H,H] weight matrices ----------------
__global__ void transpose7_kernel(const float* __restrict__ fp, const float* __restrict__ g1,
                                  const float* __restrict__ g2, const float* __restrict__ wk,
                                  const float* __restrict__ wv, const float* __restrict__ wq,
                                  const float* __restrict__ o0, float* __restrict__ out)
{
    int idx = blockIdx.x * blockDim.x + threadIdx.x;
    if (idx >= 7 * H_SZ * H_SZ) return;
    int w = idx >> 14;
    int r = idx & 16383;
    int k = r >> 7, n = r & 127;
    const float* src = (w == 0) ? fp : (w == 1) ? g1 : (w == 2) ? g2 :
                       (w == 3) ? wk : (w == 4) ? wv : (w == 5) ? wq : o0;
    out[idx] = src[n * 128 + k];
}

// ---------------- GRU scan: M=16 per CTA, 2048 CTAs (wave-quantization fix) ----------------
// grid = (32 batch-blocks of 16, 64 features), 256 threads (8 warps)
// warp w owns j in [16w, 16w+16) x 3 gates (nA-paired); M=16 (1 m-tile); K=128 (8 kt)
#define GRU_SMEM_W 98304                     // W image (24576 u32)
#define GRU_SMEM   (GRU_SMEM_W + 2 * 4096)   // + double-buffered A tile (8 cells x 32 x 16B)

__global__ __launch_bounds__(256, 2) void gru_kernel(
    const float* __restrict__ xT,     // [T][I][B]
    const uint32_t* __restrict__ P,
    const float* __restrict__ W_ih,   // [I][3H]
    const float* __restrict__ b_ih,
    const float* __restrict__ b_hh,
    float* __restrict__ hs_out)       // [B][I][H]
{
    extern __shared__ char smem[];
    uint4* s_B  = (uint4*)smem;
    uint4* s_A0 = (uint4*)(smem + GRU_SMEM_W);
    uint4* s_A1 = (uint4*)(smem + GRU_SMEM_W + 4096);

    const int i   = blockIdx.y;
    const int b0  = blockIdx.x * 16;
    const int tid = threadIdx.x;
    const int w    = tid >> 5;
    const int lane = tid & 31;
    const int g    = lane >> 2;
    const int t4   = lane & 3;

    // ---- stage W image (96KB) ----
    {
        const uint4* src = (const uint4*)(P + (size_t)i * 24576);
        for (int idx = tid; idx < 6144; idx += 256) s_B[idx] = src[idx];
    }

    // ---- per-thread gate constants (p = 2*nA + dj), r/z scaled by 0.5 ----
    float wr[4], wz[4], wn[4], bin[4], ccr[4], ccz[4], bhn[4];
#pragma unroll
    for (int p = 0; p < 4; p++) {
        const int j = 16 * w + 8 * (p >> 1) + 2 * t4 + (p & 1);
        const int base = i * G_SZ + j;
        wr[p]  = 0.5f * __ldg(&W_ih[base]);
        wz[p]  = 0.5f * __ldg(&W_ih[base + 128]);
        wn[p]  = __ldg(&W_ih[base + 256]);
        ccr[p] = 0.5f * (__ldg(&b_ih[base])       + __ldg(&b_hh[base]));
        ccz[p] = 0.5f * (__ldg(&b_ih[base + 128]) + __ldg(&b_hh[base + 128]));
        bin[p] = __ldg(&b_ih[base + 256]);
        bhn[p] = __ldg(&b_hh[base + 256]);
    }

    // h state: hq[q][hi], half2 over dj; q = j-8-block (== k-half at pack), hi = row-half
    __half2 hq[2][2];
    const __half2 hhalf = __float2half2_rn(0.5f);
    hq[0][0] = hq[0][1] = hq[1][0] = hq[1][1] = __float2half2_rn(0.0f);

    __syncthreads();

    const float* xrow = xT + (size_t)i * B_SZ + b0;

    for (int t = 0; t < T_SZ; t++) {
        uint4* sA = (t & 1) ? s_A1 : s_A0;

        // ---- pack h_t: warp w owns A-cell kt=w (its j-range == that k-range) ----
        // A reg order: {a0,a1,a2,a3} = {(row g,klo),(row g+8,klo),(row g,khi),(row g+8,khi)}
        //            =  { hq[0][0],    hq[0][1],    hq[1][0],    hq[1][1] }
        if (t > 0) {
            uint4 v;
            v.x = *reinterpret_cast<uint32_t*>(&hq[0][0]);
            v.y = *reinterpret_cast<uint32_t*>(&hq[0][1]);
            v.z = *reinterpret_cast<uint32_t*>(&hq[1][0]);
            v.w = *reinterpret_cast<uint32_t*>(&hq[1][1]);
            sA[w * 32 + lane] = v;
        }
        __syncthreads();

        // ---- prefetch x early (hide LDG under tensor phase) ----
        float xv[2];
        xv[0] = __ldg(xrow + g);
        xv[1] = __ldg(xrow + g + 8);
        xrow += I_SZ * B_SZ;

        // ---- D init with folded gate constants ----
        float D[6][4];
#pragma unroll
        for (int c = 0; c < 4; c++) {
#pragma unroll
            for (int q = 0; q < 2; q++) {
                D[q][c]     = ccr[2 * q + (c & 1)];
                D[2 + q][c] = ccz[2 * q + (c & 1)];
                D[4 + q][c] = bhn[2 * q + (c & 1)];
            }
        }

        // ---- GEMM: D[6][4] += h @ W^T ----
        if (t > 0) {
#pragma unroll
            for (int kt = 0; kt < 8; kt++) {
                uint4 a = sA[kt * 32 + lane];
                uint32_t af[4] = {a.x, a.y, a.z, a.w};
#pragma unroll
                for (int g3 = 0; g3 < 3; g3++) {
                    uint4 bv = s_B[((w * 3 + g3) * 8 + kt) * 32 + lane];
                    mma_f16(D[2 * g3 + 0], af, bv.x, bv.y);
                    mma_f16(D[2 * g3 + 1], af, bv.z, bv.w);
                }
            }
        }

        // ---- epilogue: 8 elements/thread, f16x2 gates ----
#pragma unroll
        for (int hi = 0; hi < 2; hi++) {
            const float xt = xv[hi];
            const int c0 = 2 * hi, c1 = 2 * hi + 1;
#pragma unroll
            for (int q = 0; q < 2; q++) {
                const int p0 = 2 * q, p1 = 2 * q + 1;
                const float ur0 = fmaf(xt, wr[p0], D[q][c0]);
                const float ur1 = fmaf(xt, wr[p1], D[q][c1]);
                const __half2 r2 = __hfma2(tanh2(__floats2half2_rn(ur0, ur1)), hhalf, hhalf);
                const float uz0 = fmaf(xt, wz[p0], D[2 + q][c0]);
                const float uz1 = fmaf(xt, wz[p1], D[2 + q][c1]);
                const __half2 z2 = __hfma2(tanh2(__floats2half2_rn(uz0, uz1)), hhalf, hhalf);
                const float in0 = fmaf(xt, wn[p0], bin[p0]);
                const float in1 = fmaf(xt, wn[p1], bin[p1]);
                const __half2 inn2 = __floats2half2_rn(in0, in1);
                const __half2 hn2  = __floats2half2_rn(D[4 + q][c0], D[4 + q][c1]);
                const __half2 th2  = tanh2(__hfma2(r2, hn2, inn2));
                const __half2 hold = hq[q][hi];
                hq[q][hi] = __hfma2(z2, __hsub2(hold, th2), th2);
            }
        }
    }

    // ---- write final hidden state: hs[b][i][j..j+1] ----
#pragma unroll
    for (int q = 0; q < 2; q++) {
        const int j = 16 * w + 8 * q + 2 * t4;
#pragma unroll
        for (int hi = 0; hi < 2; hi++) {
            const int b = b0 + g + 8 * hi;
            float2 f = __half22float2(hq[q][hi]);
            *(float2*)(hs_out + ((size_t)b * I_SZ + i) * H_SZ + j) = f;
        }
    }
}

// ---------------- fused tail helpers (smem-resident per-batch pipeline) ----------------
__device__ __forceinline__ void lin_smem(const float* __restrict__ Xin, const float* __restrict__ Wt,
                                         const float* __restrict__ bias, float* __restrict__ Yout,
                                         float* __restrict__ gout, int relu, int w, int l)
{
    const int r0 = w * 8;
    float acc[8][4];
#pragma unroll
    for (int rr = 0; rr < 8; rr++)
#pragma unroll
        for (int c = 0; c < 4; c++) acc[rr][c] = 0.f;
#pragma unroll 4
    for (int k = 0; k < 128; k++) {
        float wv[4];
#pragma unroll
        for (int c = 0; c < 4; c++) wv[c] = __ldg(&Wt[k * 128 + l + 32 * c]);
#pragma unroll
        for (int rr = 0; rr < 8; rr++) {
            const float xv = Xin[(r0 + rr) * 128 + k];
#pragma unroll
            for (int c = 0; c < 4; c++) acc[rr][c] = fmaf(xv, wv[c], acc[rr][c]);
        }
    }
#pragma unroll
    for (int rr = 0; rr < 8; rr++)
#pragma unroll
        for (int c = 0; c < 4; c++) {
            const int n = l + 32 * c;
            float v = acc[rr][c] + __ldg(&bias[n]);
            if (relu) v = fmaxf(v, 0.f);
            Yout[(r0 + rr) * 128 + n] = v;
            if (gout) gout[(size_t)(r0 + rr) * 128 + n] = v;
        }
}

__device__ __forceinline__ void adj_smem(const float* __restrict__ Xin, const float* __restrict__ adj,
                                         float* __restrict__ Yout, int w, int l)
{
    const int i0 = w * 8;
    float acc[8][4];
#pragma unroll
    for (int ii = 0; ii < 8; ii++)
#pragma unroll
        for (int c = 0; c < 4; c++) acc[ii][c] = 0.f;
#pragma unroll 4
    for (int j = 0; j < 64; j++) {
        float hv[4];
#pragma unroll
        for (int c = 0; c < 4; c++) hv[c] = Xin[j * 128 + l + 32 * c];
#pragma unroll
        for (int ii = 0; ii < 8; ii++) {
            const float a = __ldg(&adj[(i0 + ii) * 64 + j]);
#pragma unroll
            for (int c = 0; c < 4; c++) acc[ii][c] = fmaf(a, hv[c], acc[ii][c]);
        }
    }
#pragma unroll
    for (int ii = 0; ii < 8; ii++)
#pragma unroll
        for (int c = 0; c < 4; c++)
            Yout[(i0 + ii) * 128 + l + 32 * c] = acc[ii][c];
}

// one block per batch: hs -> ht(out) -> adj -> g1 -> adj -> g2 -> attention -> out
#define TAIL_SMEM (16384 * 4 + 4 * (128 * 4 + 64 + 2) + 256)

__global__ __launch_bounds__(256) void tail_kernel(
    const float* __restrict__ hs, const float* __restrict__ adj,
    const float* __restrict__ fpT, const float* __restrict__ fp_b,
    const float* __restrict__ g1T, const float* __restrict__ g1_b,
    const float* __restrict__ g2T, const float* __restrict__ g2_b,
    const float* __restrict__ wqT, const float* __restrict__ wq_b,
    const float* __restrict__ wk_w, const float* __restrict__ wk_b,
    const float* __restrict__ wvT, const float* __restrict__ wv_b,
    const float* __restrict__ o0T, const float* __restrict__ o0_b,
    float* __restrict__ ht_out, float* __restrict__ out)
{
    extern __shared__ float sm[];
    float* Xs = sm;                  // [64][128]
    float* Zs = sm + 8192;           // [64][128]
    float* q  = sm + 16384;
    float* u  = q + 128;
    float* s  = u + 128;
    float* wc = s + 128;
    float* ev = wc + 128;
    float* red = ev + 64;

    const int b = blockIdx.x;
    const int tid = threadIdx.x, w = tid >> 5, l = tid & 31;

    for (int idx = tid; idx < 8192; idx += 256)
        Xs[idx] = hs[(size_t)b * 8192 + idx];
    __syncthreads();

    lin_smem(Xs, fpT, fp_b, Zs, ht_out + (size_t)b * 8192, 0, w, l);
    __syncthreads();
    adj_smem(Zs, adj, Xs, w, l);
    __syncthreads();
    lin_smem(Xs, g1T, g1_b, Zs, nullptr, 1, w, l);
    __syncthreads();
    adj_smem(Zs, adj, Xs, w, l);
    __syncthreads();
    lin_smem(Xs, g2T, g2_b, Zs, nullptr, 1, w, l);   // Zs = ctx
    __syncthreads();

    // ---- attention on ctx (Zs) ----
    if (tid < 128) {
        float acc = __ldg(&wq_b[tid]);
        for (int k = 0; k < 128; k++)
            acc = fmaf(Zs[63 * 128 + k], __ldg(&wqT[k * 128 + tid]), acc);
        q[tid] = acc;
    }
    __syncthreads();
    if (tid < 128) {
        float acc = 0.f;
        for (int n = 0; n < 128; n++)
            acc = fmaf(q[n], __ldg(&wk_w[n * 128 + tid]), acc);
        u[tid] = acc;
    }
    if (tid == 128) {
        float c = 0.f;
        for (int n = 0; n < 128; n++) c = fmaf(q[n], __ldg(&wk_b[n]), c);
        red[0] = c;
    }
    __syncthreads();
    if (tid < 64) {
        float e = red[0];
        for (int k = 0; k < 128; k++) e = fmaf(Zs[tid * 128 + k], u[k], e);
        ev[tid] = e;
    }
    __syncthreads();
    if (tid == 0) {
        float mx = -1e30f;
        for (int ii = 0; ii < 64; ii++) mx = fmaxf(mx, ev[ii]);
        float smm = 0.f;
        for (int ii = 0; ii < 64; ii++) smm += __expf(ev[ii] - mx);
        red[0] = mx; red[1] = 1.0f / smm;
    }
    __syncthreads();
    if (tid < 64) ev[tid] = __expf(ev[tid] - red[0]) * red[1];
    __syncthreads();
    if (tid < 128) {
        float acc = 0.f;
        for (int ii = 0; ii < 64; ii++) acc = fmaf(ev[ii], Zs[ii * 128 + tid], acc);
        s[tid] = acc;
    }
    __syncthreads();
    if (tid < 128) {
        float acc = __ldg(&wv_b[tid]);
        for (int k = 0; k < 128; k++) acc = fmaf(s[k], __ldg(&wvT[k * 128 + tid]), acc);
        wc[tid] = acc;
    }
    __syncthreads();
    if (tid < 128) {
        float acc = __ldg(&o0_b[tid]);
        for (int m = 0; m < 128; m++) acc = fmaf(wc[m], __ldg(&o0T[m * 128 + tid]), acc);
        out[(size_t)b * 128 + tid] = fmaxf(acc, 0.f);
    }
}

// ---------------- launch ----------------
extern "C" void kernel_launch(void* const* d_in, const int* in_sizes, int n_in,
                              void* d_out, int out_size)
{
    const float* x     = (const float*)d_in[0];
    const float* W_ih  = (const float*)d_in[1];
    const float* W_hh  = (const float*)d_in[2];
    const float* b_ih  = (const float*)d_in[3];
    const float* b_hh  = (const float*)d_in[4];
    const float* fp_w  = (const float*)d_in[5];
    const float* fp_b  = (const float*)d_in[6];
    const float* g1_w  = (const float*)d_in[7];
    const float* g1_b  = (const float*)d_in[8];
    const float* g2_w  = (const float*)d_in[9];
    const float* g2_b  = (const float*)d_in[10];
    const float* wq_w  = (const float*)d_in[11];
    const float* wq_b  = (const float*)d_in[12];
    const float* wk_w  = (const float*)d_in[13];
    const float* wk_b  = (const float*)d_in[14];
    const float* wv_w  = (const float*)d_in[15];
    const float* wv_b  = (const float*)d_in[16];
    const float* o0_w  = (const float*)d_in[17];
    const float* o0_b  = (const float*)d_in[18];
    const float* adj   = (const float*)d_in[19];

    float* out = (float*)d_out;
    float* ht_out = out + B_SZ * H_SZ;

    uint32_t* P;
    float *hs, *A, *Wt;
    cudaGetSymbolAddress((void**)&P,  g_P);
    cudaGetSymbolAddress((void**)&hs, g_hs);
    cudaGetSymbolAddress((void**)&A,  g_A);
    cudaGetSymbolAddress((void**)&Wt, g_Wt);

    cudaFuncSetAttribute(gru_kernel, cudaFuncAttributeMaxDynamicSharedMemorySize, GRU_SMEM);
    cudaFuncSetAttribute(tail_kernel, cudaFuncAttributeMaxDynamicSharedMemorySize, TAIL_SMEM);

    // prep
    pack_whh_kernel<<<(I_SZ * 24576 + 255) / 256, 256>>>(W_hh, P);
    transpose7_kernel<<<(7 * H_SZ * H_SZ + 255) / 256, 256>>>(fp_w, g1_w, g2_w, wk_w, wv_w, wq_w, o0_w, Wt);
    xt_kernel<<<(B_SZ * T_SZ * I_SZ + 255) / 256, 256>>>(x, A);

    const float* fpT = Wt + 0 * 16384;
    const float* g1T = Wt + 1 * 16384;
    const float* g2T = Wt + 2 * 16384;
    const float* wvT = Wt + 4 * 16384;
    const float* wqT = Wt + 5 * 16384;
    const float* o0T = Wt + 6 * 16384;

    // 1) GRU scan -> hs (M=16 per CTA, 2048 CTAs)
    gru_kernel<<<dim3(32, 64), 256, GRU_SMEM>>>(A, P, W_ih, b_ih, b_hh, hs);

    // 2) fused tail
    tail_kernel<<<B_SZ, 256, TAIL_SMEM>>>(hs, adj,
                                          fpT, fp_b, g1T, g1_b, g2T, g2_b,
                                          wqT, wq_b, wk_w, wk_b, wvT, wv_b,
                                          o0T, o0_b, ht_out, out);
}

// round 13
// speedup vs baseline: 1.1334x; 1.1334x over previous
#include <cuda_runtime.h>
#include <cuda_bf16.h>
#include <cuda_fp16.h>
#include <math.h>
#include <stdint.h>

// Problem constants
#define B_SZ 512
#define T_SZ 64
#define I_SZ 64
#define H_SZ 128
#define G_SZ 384   // 3*H

// ---------------- device scratch (no allocations allowed) ----------------
__device__ uint32_t g_P [I_SZ * 24576];             // per-feature W_hh, fp16 paired-fragment layout
__device__ float g_hs[B_SZ * I_SZ * H_SZ];          // GRU final hidden
__device__ float g_A [B_SZ * I_SZ * H_SZ];          // xT
__device__ float g_Wt[7 * H_SZ * H_SZ];             // transposed tail weights

__device__ __forceinline__ void mma_f16(float* d, const uint32_t* a, uint32_t b0, uint32_t b1) {
    asm volatile(
        "mma.sync.aligned.m16n8k16.row.col.f32.f16.f16.f32 "
        "{%0,%1,%2,%3}, {%4,%5,%6,%7}, {%8,%9}, {%0,%1,%2,%3};"
        : "+f"(d[0]), "+f"(d[1]), "+f"(d[2]), "+f"(d[3])
        : "r"(a[0]), "r"(a[1]), "r"(a[2]), "r"(a[3]), "r"(b0), "r"(b1));
}

__device__ __forceinline__ __half2 tanh2(__half2 v) {
    uint32_t o, in = *reinterpret_cast<uint32_t*>(&v);
    asm("tanh.approx.f16x2 %0, %1;" : "=r"(o) : "r"(in));
    return *reinterpret_cast<__half2*>(&o);
}

__device__ __forceinline__ __half2 cvt2(float a, float b) {
    // packs (a,b) -> half2 {lo=a, hi=b} in one cvt
    __half2 h;
    asm("cvt.rn.f16x2.f32 %0, %1, %2;" : "=r"(*(uint32_t*)&h) : "f"(b), "f"(a));
    return h;
}

// ---------------- pack W_hh: fp16, nA-paired B-fragment layout, r/z rows pre-scaled 0.5 ----------------
// P[i][ (((w*3+g3)*8+kt)*32 + lane)*4 + s ], s: nA = s>>1, reg = s&1
// k0 = 16kt + 8reg + 2(lane&3) ; j = 16w + 8nA + (lane>>2) ; row = g3*128 + j
__global__ void pack_whh_kernel(const float* __restrict__ W_hh, uint32_t* __restrict__ P)
{
    int idx = blockIdx.x * blockDim.x + threadIdx.x;
    if (idx >= I_SZ * 24576) return;
    int i = idx / 24576;
    int r = idx % 24576;
    int w  = r / 3072; r %= 3072;
    int g3 = r / 1024; r %= 1024;
    int kt = r / 128;  r %= 128;
    int lane = r >> 2;
    int s = r & 3;
    int nA = s >> 1, reg = s & 1;
    int k0 = 16 * kt + 8 * reg + 2 * (lane & 3);
    int j  = 16 * w + 8 * nA + (lane >> 2);
    float scale = (g3 < 2) ? 0.5f : 1.0f;   // fold sigmoid's /2 into r,z weights
    const float* src = W_hh + ((size_t)i * G_SZ + g3 * 128 + j) * H_SZ + k0;
    __half2 h2 = __floats2half2_rn(scale * src[0], scale * src[1]);
    P[idx] = *reinterpret_cast<uint32_t*>(&h2);
}

// ---------------- transpose x: xT[t][i][b] = x[b][t][i] ----------------
__global__ void xt_kernel(const float* __restrict__ x, float* __restrict__ xT)
{
    int idx = blockIdx.x * blockDim.x + threadIdx.x;
    if (idx >= B_SZ * T_SZ * I_SZ) return;
    int b = idx & 511;
    int r = idx >> 9;
    int i = r & 63;
    int t = r >> 6;
    xT[idx] = x[((size_t)b * T_SZ + t) * I_SZ + i];
}

// ---------------- transpose the 7 [H,H] weight matrices ----------------
__global__ void transpose7_kernel(const float* __restrict__ fp, const float* __restrict__ g1,
                                  const float* __restrict__ g2, const float* __restrict__ wk,
                                  const float* __restrict__ wv, const float* __restrict__ wq,
                                  const float* __restrict__ o0, float* __restrict__ out)
{
    int idx = blockIdx.x * blockDim.x + threadIdx.x;
    if (idx >= 7 * H_SZ * H_SZ) return;
    int w = idx >> 14;
    int r = idx & 16383;
    int k = r >> 7, n = r & 127;
    const float* src = (w == 0) ? fp : (w == 1) ? g1 : (w == 2) ? g2 :
                       (w == 3) ? wk : (w == 4) ? wv : (w == 5) ? wq : o0;
    out[idx] = src[n * 128 + k];
}

// ---------------- GRU scan: R8 geometry (M=32, grid 1024) + half2 epilogue (register diet) ----------------
// grid = (16 batch-blocks of 32, 64 features), 256 threads (8 warps)
// warp w owns j in [16w, 16w+16) x 3 gates (nA-paired); M=32 (2 m-tiles); K=128 (8 kt)
#define GRU_SMEM_W 98304                     // W image (24576 u32)
#define GRU_SMEM   (GRU_SMEM_W + 2 * 8192)   // + double-buffered A tile (16 cells x 32 x 16B)

__global__ __launch_bounds__(256, 2) void gru_kernel(
    const float* __restrict__ xT,     // [T][I][B]
    const uint32_t* __restrict__ P,
    const float* __restrict__ W_ih,   // [I][3H]
    const float* __restrict__ b_ih,
    const float* __restrict__ b_hh,
    float* __restrict__ hs_out)       // [B][I][H]
{
    extern __shared__ char smem[];
    uint4* s_B  = (uint4*)smem;
    uint4* s_A0 = (uint4*)(smem + GRU_SMEM_W);
    uint4* s_A1 = (uint4*)(smem + GRU_SMEM_W + 8192);

    const int i   = blockIdx.y;
    const int b0  = blockIdx.x * 32;
    const int tid = threadIdx.x;
    const int w    = tid >> 5;
    const int lane = tid & 31;
    const int g    = lane >> 2;
    const int t4   = lane & 3;

    // ---- stage W image (96KB) ----
    {
        const uint4* src = (const uint4*)(P + (size_t)i * 24576);
        for (int idx = tid; idx < 6144; idx += 256) s_B[idx] = src[idx];
    }

    // ---- per-thread gate constants as half2 over dj (q = nA in {0,1}), r/z scaled by 0.5 ----
    __half2 wr2[2], wz2[2], wn2[2], bin2[2], ccr2[2], ccz2[2], bhn2[2];
#pragma unroll
    for (int q = 0; q < 2; q++) {
        const int j = 16 * w + 8 * q + 2 * t4;
        const int base = i * G_SZ + j;
        wr2[q]  = __floats2half2_rn(0.5f * __ldg(&W_ih[base]),       0.5f * __ldg(&W_ih[base + 1]));
        wz2[q]  = __floats2half2_rn(0.5f * __ldg(&W_ih[base + 128]), 0.5f * __ldg(&W_ih[base + 129]));
        wn2[q]  = __floats2half2_rn(__ldg(&W_ih[base + 256]),        __ldg(&W_ih[base + 257]));
        ccr2[q] = __floats2half2_rn(0.5f * (__ldg(&b_ih[base])       + __ldg(&b_hh[base])),
                                    0.5f * (__ldg(&b_ih[base + 1])   + __ldg(&b_hh[base + 1])));
        ccz2[q] = __floats2half2_rn(0.5f * (__ldg(&b_ih[base + 128]) + __ldg(&b_hh[base + 128])),
                                    0.5f * (__ldg(&b_ih[base + 129]) + __ldg(&b_hh[base + 129])));
        bin2[q] = __floats2half2_rn(__ldg(&b_ih[base + 256]), __ldg(&b_ih[base + 257]));
        bhn2[q] = __floats2half2_rn(__ldg(&b_hh[base + 256]), __ldg(&b_hh[base + 257]));
    }

    // h state: hq[mt][q][hi], half2 over dj
    __half2 hq[2][2][2];
    const __half2 hhalf = __float2half2_rn(0.5f);
#pragma unroll
    for (int mt = 0; mt < 2; mt++)
#pragma unroll
        for (int q = 0; q < 2; q++)
            hq[mt][q][0] = hq[mt][q][1] = __float2half2_rn(0.0f);

    __syncthreads();

    const float* xrow = xT + (size_t)i * B_SZ + b0;

    for (int t = 0; t < T_SZ; t++) {
        uint4* sA = (t & 1) ? s_A1 : s_A0;

        // ---- pack h_t: warp w owns A-cells kt=w; A order {(g,klo),(g+8,klo),(g,khi),(g+8,khi)} ----
        if (t > 0) {
#pragma unroll
            for (int mt = 0; mt < 2; mt++) {
                uint4 v;
                v.x = *reinterpret_cast<uint32_t*>(&hq[mt][0][0]);
                v.y = *reinterpret_cast<uint32_t*>(&hq[mt][0][1]);
                v.z = *reinterpret_cast<uint32_t*>(&hq[mt][1][0]);
                v.w = *reinterpret_cast<uint32_t*>(&hq[mt][1][1]);
                sA[(w * 2 + mt) * 32 + lane] = v;
            }
        }
        __syncthreads();

        // ---- prefetch x early (hide LDG under tensor phase), broadcast to half2 ----
        __half2 x2[2][2];
#pragma unroll
        for (int mt = 0; mt < 2; mt++)
#pragma unroll
            for (int hi = 0; hi < 2; hi++)
                x2[mt][hi] = __float2half2_rn(__ldg(xrow + 16 * mt + g + 8 * hi));
        xrow += I_SZ * B_SZ;

        // ---- D zero-init ----
        float D[2][6][4];
#pragma unroll
        for (int mt = 0; mt < 2; mt++)
#pragma unroll
            for (int n = 0; n < 6; n++)
#pragma unroll
                for (int c = 0; c < 4; c++) D[mt][n][c] = 0.0f;

        // ---- GEMM: D += h @ W^T ----
        if (t > 0) {
#pragma unroll
            for (int kt = 0; kt < 8; kt++) {
                uint4 a0 = sA[(kt * 2 + 0) * 32 + lane];
                uint4 a1 = sA[(kt * 2 + 1) * 32 + lane];
                uint32_t af0[4] = {a0.x, a0.y, a0.z, a0.w};
                uint32_t af1[4] = {a1.x, a1.y, a1.z, a1.w};
#pragma unroll
                for (int g3 = 0; g3 < 3; g3++) {
                    uint4 bv = s_B[((w * 3 + g3) * 8 + kt) * 32 + lane];
                    mma_f16(D[0][2 * g3 + 0], af0, bv.x, bv.y);
                    mma_f16(D[0][2 * g3 + 1], af0, bv.z, bv.w);
                    mma_f16(D[1][2 * g3 + 0], af1, bv.x, bv.y);
                    mma_f16(D[1][2 * g3 + 1], af1, bv.z, bv.w);
                }
            }
        }

        // ---- epilogue fully in half2 domain ----
#pragma unroll
        for (int mt = 0; mt < 2; mt++) {
#pragma unroll
            for (int hi = 0; hi < 2; hi++) {
                const __half2 xt2 = x2[mt][hi];
                const int c0 = 2 * hi, c1 = 2 * hi + 1;
#pragma unroll
                for (int q = 0; q < 2; q++) {
                    __half2 ur2 = __hadd2(cvt2(D[mt][q][c0], D[mt][q][c1]), ccr2[q]);
                    ur2 = __hfma2(xt2, wr2[q], ur2);
                    const __half2 r2 = __hfma2(tanh2(ur2), hhalf, hhalf);
                    __half2 uz2 = __hadd2(cvt2(D[mt][2 + q][c0], D[mt][2 + q][c1]), ccz2[q]);
                    uz2 = __hfma2(xt2, wz2[q], uz2);
                    const __half2 z2 = __hfma2(tanh2(uz2), hhalf, hhalf);
                    const __half2 inn2 = __hfma2(xt2, wn2[q], bin2[q]);
                    const __half2 hn2  = __hadd2(cvt2(D[mt][4 + q][c0], D[mt][4 + q][c1]), bhn2[q]);
                    const __half2 th2  = tanh2(__hfma2(r2, hn2, inn2));
                    const __half2 hold = hq[mt][q][hi];
                    hq[mt][q][hi] = __hfma2(z2, __hsub2(hold, th2), th2);
                }
            }
        }
    }

    // ---- write final hidden state: hs[b][i][j..j+1] ----
#pragma unroll
    for (int mt = 0; mt < 2; mt++)
#pragma unroll
        for (int q = 0; q < 2; q++) {
            const int j = 16 * w + 8 * q + 2 * t4;
#pragma unroll
            for (int hi = 0; hi < 2; hi++) {
                const int b = b0 + 16 * mt + g + 8 * hi;
                float2 f = __half22float2(hq[mt][q][hi]);
                *(float2*)(hs_out + ((size_t)b * I_SZ + i) * H_SZ + j) = f;
            }
        }
}

// ---------------- fused tail helpers (smem-resident per-batch pipeline) ----------------
__device__ __forceinline__ void lin_smem(const float* __restrict__ Xin, const float* __restrict__ Wt,
                                         const float* __restrict__ bias, float* __restrict__ Yout,
                                         float* __restrict__ gout, int relu, int w, int l)
{
    const int r0 = w * 8;
    float acc[8][4];
#pragma unroll
    for (int rr = 0; rr < 8; rr++)
#pragma unroll
        for (int c = 0; c < 4; c++) acc[rr][c] = 0.f;
#pragma unroll 4
    for (int k = 0; k < 128; k++) {
        float wv[4];
#pragma unroll
        for (int c = 0; c < 4; c++) wv[c] = __ldg(&Wt[k * 128 + l + 32 * c]);
#pragma unroll
        for (int rr = 0; rr < 8; rr++) {
            const float xv = Xin[(r0 + rr) * 128 + k];
#pragma unroll
            for (int c = 0; c < 4; c++) acc[rr][c] = fmaf(xv, wv[c], acc[rr][c]);
        }
    }
#pragma unroll
    for (int rr = 0; rr < 8; rr++)
#pragma unroll
        for (int c = 0; c < 4; c++) {
            const int n = l + 32 * c;
            float v = acc[rr][c] + __ldg(&bias[n]);
            if (relu) v = fmaxf(v, 0.f);
            Yout[(r0 + rr) * 128 + n] = v;
            if (gout) gout[(size_t)(r0 + rr) * 128 + n] = v;
        }
}

__device__ __forceinline__ void adj_smem(const float* __restrict__ Xin, const float* __restrict__ adj,
                                         float* __restrict__ Yout, int w, int l)
{
    const int i0 = w * 8;
    float acc[8][4];
#pragma unroll
    for (int ii = 0; ii < 8; ii++)
#pragma unroll
        for (int c = 0; c < 4; c++) acc[ii][c] = 0.f;
#pragma unroll 4
    for (int j = 0; j < 64; j++) {
        float hv[4];
#pragma unroll
        for (int c = 0; c < 4; c++) hv[c] = Xin[j * 128 + l + 32 * c];
#pragma unroll
        for (int ii = 0; ii < 8; ii++) {
            const float a = __ldg(&adj[(i0 + ii) * 64 + j]);
#pragma unroll
            for (int c = 0; c < 4; c++) acc[ii][c] = fmaf(a, hv[c], acc[ii][c]);
        }
    }
#pragma unroll
    for (int ii = 0; ii < 8; ii++)
#pragma unroll
        for (int c = 0; c < 4; c++)
            Yout[(i0 + ii) * 128 + l + 32 * c] = acc[ii][c];
}

// one block per batch: hs -> ht(out) -> adj -> g1 -> adj -> g2 -> attention -> out
#define TAIL_SMEM (16384 * 4 + 4 * (128 * 4 + 64 + 2) + 256)

__global__ __launch_bounds__(256) void tail_kernel(
    const float* __restrict__ hs, const float* __restrict__ adj,
    const float* __restrict__ fpT, const float* __restrict__ fp_b,
    const float* __restrict__ g1T, const float* __restrict__ g1_b,
    const float* __restrict__ g2T, const float* __restrict__ g2_b,
    const float* __restrict__ wqT, const float* __restrict__ wq_b,
    const float* __restrict__ wk_w, const float* __restrict__ wk_b,
    const float* __restrict__ wvT, const float* __restrict__ wv_b,
    const float* __restrict__ o0T, const float* __restrict__ o0_b,
    float* __restrict__ ht_out, float* __restrict__ out)
{
    extern __shared__ float sm[];
    float* Xs = sm;                  // [64][128]
    float* Zs = sm + 8192;           // [64][128]
    float* q  = sm + 16384;
    float* u  = q + 128;
    float* s  = u + 128;
    float* wc = s + 128;
    float* ev = wc + 128;
    float* red = ev + 64;

    const int b = blockIdx.x;
    const int tid = threadIdx.x, w = tid >> 5, l = tid & 31;

    for (int idx = tid; idx < 8192; idx += 256)
        Xs[idx] = hs[(size_t)b * 8192 + idx];
    __syncthreads();

    lin_smem(Xs, fpT, fp_b, Zs, ht_out + (size_t)b * 8192, 0, w, l);
    __syncthreads();
    adj_smem(Zs, adj, Xs, w, l);
    __syncthreads();
    lin_smem(Xs, g1T, g1_b, Zs, nullptr, 1, w, l);
    __syncthreads();
    adj_smem(Zs, adj, Xs, w, l);
    __syncthreads();
    lin_smem(Xs, g2T, g2_b, Zs, nullptr, 1, w, l);   // Zs = ctx
    __syncthreads();

    // ---- attention on ctx (Zs) ----
    if (tid < 128) {
        float acc = __ldg(&wq_b[tid]);
        for (int k = 0; k < 128; k++)
            acc = fmaf(Zs[63 * 128 + k], __ldg(&wqT[k * 128 + tid]), acc);
        q[tid] = acc;
    }
    __syncthreads();
    if (tid < 128) {
        float acc = 0.f;
        for (int n = 0; n < 128; n++)
            acc = fmaf(q[n], __ldg(&wk_w[n * 128 + tid]), acc);
        u[tid] = acc;
    }
    if (tid == 128) {
        float c = 0.f;
        for (int n = 0; n < 128; n++) c = fmaf(q[n], __ldg(&wk_b[n]), c);
        red[0] = c;
    }
    __syncthreads();
    if (tid < 64) {
        float e = red[0];
        for (int k = 0; k < 128; k++) e = fmaf(Zs[tid * 128 + k], u[k], e);
        ev[tid] = e;
    }
    __syncthreads();
    if (tid == 0) {
        float mx = -1e30f;
        for (int ii = 0; ii < 64; ii++) mx = fmaxf(mx, ev[ii]);
        float smm = 0.f;
        for (int ii = 0; ii < 64; ii++) smm += __expf(ev[ii] - mx);
        red[0] = mx; red[1] = 1.0f / smm;
    }
    __syncthreads();
    if (tid < 64) ev[tid] = __expf(ev[tid] - red[0]) * red[1];
    __syncthreads();
    if (tid < 128) {
        float acc = 0.f;
        for (int ii = 0; ii < 64; ii++) acc = fmaf(ev[ii], Zs[ii * 128 + tid], acc);
        s[tid] = acc;
    }
    __syncthreads();
    if (tid < 128) {
        float acc = __ldg(&wv_b[tid]);
        for (int k = 0; k < 128; k++) acc = fmaf(s[k], __ldg(&wvT[k * 128 + tid]), acc);
        wc[tid] = acc;
    }
    __syncthreads();
    if (tid < 128) {
        float acc = __ldg(&o0_b[tid]);
        for (int m = 0; m < 128; m++) acc = fmaf(wc[m], __ldg(&o0T[m * 128 + tid]), acc);
        out[(size_t)b * 128 + tid] = fmaxf(acc, 0.f);
    }
}

// ---------------- launch ----------------
extern "C" void kernel_launch(void* const* d_in, const int* in_sizes, int n_in,
                              void* d_out, int out_size)
{
    const float* x     = (const float*)d_in[0];
    const float* W_ih  = (const float*)d_in[1];
    const float* W_hh  = (const float*)d_in[2];
    const float* b_ih  = (const float*)d_in[3];
    const float* b_hh  = (const float*)d_in[4];
    const float* fp_w  = (const float*)d_in[5];
    const float* fp_b  = (const float*)d_in[6];
    const float* g1_w  = (const float*)d_in[7];
    const float* g1_b  = (const float*)d_in[8];
    const float* g2_w  = (const float*)d_in[9];
    const float* g2_b  = (const float*)d_in[10];
    const float* wq_w  = (const float*)d_in[11];
    const float* wq_b  = (const float*)d_in[12];
    const float* wk_w  = (const float*)d_in[13];
    const float* wk_b  = (const float*)d_in[14];
    const float* wv_w  = (const float*)d_in[15];
    const float* wv_b  = (const float*)d_in[16];
    const float* o0_w  = (const float*)d_in[17];
    const float* o0_b  = (const float*)d_in[18];
    const float* adj   = (const float*)d_in[19];

    float* out = (float*)d_out;
    float* ht_out = out + B_SZ * H_SZ;

    uint32_t* P;
    float *hs, *A, *Wt;
    cudaGetSymbolAddress((void**)&P,  g_P);
    cudaGetSymbolAddress((void**)&hs, g_hs);
    cudaGetSymbolAddress((void**)&A,  g_A);
    cudaGetSymbolAddress((void**)&Wt, g_Wt);

    cudaFuncSetAttribute(gru_kernel, cudaFuncAttributeMaxDynamicSharedMemorySize, GRU_SMEM);
    cudaFuncSetAttribute(tail_kernel, cudaFuncAttributeMaxDynamicSharedMemorySize, TAIL_SMEM);

    // prep
    pack_whh_kernel<<<(I_SZ * 24576 + 255) / 256, 256>>>(W_hh, P);
    transpose7_kernel<<<(7 * H_SZ * H_SZ + 255) / 256, 256>>>(fp_w, g1_w, g2_w, wk_w, wv_w, wq_w, o0_w, Wt);
    xt_kernel<<<(B_SZ * T_SZ * I_SZ + 255) / 256, 256>>>(x, A);

    const float* fpT = Wt + 0 * 16384;
    const float* g1T = Wt + 1 * 16384;
    const float* g2T = Wt + 2 * 16384;
    const float* wvT = Wt + 4 * 16384;
    const float* wqT = Wt + 5 * 16384;
    const float* o0T = Wt + 6 * 16384;

    // 1) GRU scan -> hs (M=32 per CTA, 1024 CTAs — R8 geometry)
    gru_kernel<<<dim3(16, 64), 256, GRU_SMEM>>>(A, P, W_ih, b_ih, b_hh, hs);

    // 2) fused tail
    tail_kernel<<<B_SZ, 256, TAIL_SMEM>>>(hs, adj,
                                          fpT, fp_b, g1T, g1_b, g2T, g2_b,
                                          wqT, wq_b, wk_w, wk_b, wvT, wv_b,
                                          o0T, o0_b, ht_out, out);
}